// round 1
// baseline (speedup 1.0000x reference)
#include <cuda_runtime.h>
#include <cuda_bf16.h>
#include <cstdint>
#include <cstdio>

// Problem constants
#define BB   8
#define SS   2048
#define DD   1024
#define KK   256
#define NFFT 2048
#define K2   512   // 2*KK (stacked real/imag)

// ---------------- device scratch (no allocations allowed) ----------------
__device__ __align__(256) __nv_bfloat16 g_basis1[K2 * SS];        // A1[k][s]: rows 0..255 cos, 256..511 -sin
__device__ __align__(256) __nv_bfloat16 g_basis2[SS * K2];        // A2[s][j]: irfft basis with c_k/N folded in
__device__ __align__(256) __nv_bfloat16 g_wt[KK * KK];            // WT[j][k] = W[k][j]
__device__ __align__(256) __nv_bfloat16 g_xbf[BB * SS * DD];      // bf16(x)
__device__ __align__(256) float         g_X[BB * K2 * DD];        // Xr rows 0..255, Xi rows 256..511
__device__ __align__(256) __nv_bfloat16 g_xwr[BB * KK * DD];      // Re(x_weighted) bf16
__device__ __align__(256) float         g_dpart[BB * KK * DD];    // xwr - Xr (fp32, pre-interference)
__device__ __align__(256) __nv_bfloat16 g_delta[BB * K2 * DD];    // stacked [deltar; deltai] bf16

// ---------------- helpers ----------------
__device__ __forceinline__ int freq_of(int k) {
    // np.linspace(0, 512, 256).astype(int64); numpy pins the endpoint exactly.
    if (k == 255) return 512;
    return (int)((double)k * (512.0 / 255.0));
}

__device__ __forceinline__ uint32_t smem_u32(const void* p) {
    return (uint32_t)__cvta_generic_to_shared(p);
}

// ---------------- basis construction (runs every launch; deterministic) ----------------
__global__ void k_basis() {
    int idx = blockIdx.x * blockDim.x + threadIdx.x;
    if (idx >= K2 * SS) return;
    int row = idx >> 11;       // 0..511
    int s   = idx & 2047;
    int k   = row & 255;
    int f   = freq_of(k);
    int m   = (f * s) & (NFFT - 1);
    float ang = (float)m * (6.28318530717958647692f / (float)NFFT);
    float sv, cv;
    sincosf(ang, &sv, &cv);
    // forward DFT basis: Xr = sum cos * x ; Xi = -sum sin * x
    float v1 = (row < KK) ? cv : -sv;
    g_basis1[idx] = __float2bfloat16(v1);
    // inverse (irfft of sparse delta): (c_k/N) * (cos*Re - sin*Im)
    float scale = ((k == 0) ? 1.0f : 2.0f) * (1.0f / (float)NFFT);
    float v2 = (row < KK) ? (scale * cv) : (-scale * sv);
    g_basis2[s * K2 + row] = __float2bfloat16(v2);
}

__global__ void k_wt(const float* __restrict__ W) {
    int idx = blockIdx.x * blockDim.x + threadIdx.x;   // 65536
    if (idx >= KK * KK) return;
    int j = idx >> 8, k = idx & 255;
    g_wt[idx] = __float2bfloat16(W[k * KK + j]);
}

__global__ void k_convert(const float* __restrict__ x) {
    int i = blockIdx.x * blockDim.x + threadIdx.x;     // over float4s
    if (i >= (BB * SS * DD) / 4) return;
    float4 v = ((const float4*)x)[i];
    __nv_bfloat162* o = (__nv_bfloat162*)g_xbf;
    o[2 * i]     = __floats2bfloat162_rn(v.x, v.y);
    o[2 * i + 1] = __floats2bfloat162_rn(v.z, v.w);
}

// elementwise: complex weight, imag delta, partial real delta
__global__ void k_elem(const float* __restrict__ mag, const float* __restrict__ ph) {
    int idx = blockIdx.x * blockDim.x + threadIdx.x;   // BB*KK*DD = 2M
    if (idx >= BB * KK * DD) return;
    int b = idx >> 18;
    int r = idx & 262143;
    int k = r >> 10;
    int d = r & 1023;
    size_t xb = (size_t)b * (K2 * DD);
    float Xr = g_X[xb + ((size_t)k << 10) + d];
    float Xi = g_X[xb + ((size_t)(k + KK) << 10) + d];
    float mg = mag[(k << 10) + d];
    float p  = ph[(k << 10) + d];
    float sp, cp;
    sincosf(p, &sp, &cp);
    float cr = mg * cp, ci = mg * sp;
    float xwr = Xr * cr - Xi * ci;
    float xwi = Xr * ci + Xi * cr;
    g_xwr[idx]   = __float2bfloat16(xwr);
    g_dpart[idx] = xwr - Xr;
    g_delta[xb + ((size_t)(k + KK) << 10) + d] = __float2bfloat16(xwi - Xi);
}

// ---------------- tiled bf16 mma GEMM: C[m][n] = sum_k A[m][k] * B[k][n] ----------------
// MODE 0: fp32 store (G1)
// MODE 1: bf16 store: aux + 0.1*acc (interference -> deltar)
// MODE 2: fp32 store: acc + 2*aux   (irfft contrib + residual*2)
#define BM 128
#define BN 128
#define BKg 32

template <int MODE>
__global__ __launch_bounds__(256) void gemm_mma(
    const __nv_bfloat16* __restrict__ A, size_t sA, int ldA,
    const __nv_bfloat16* __restrict__ Bm, size_t sB, int ldB,
    void* __restrict__ Cv, size_t sC, int ldC,
    const float* __restrict__ aux, size_t sAux,
    int Kdim)
{
    __shared__ __align__(16) __nv_bfloat16 As[BM][40];    // stride 80B (16B-mult, conflict-free)
    __shared__ __align__(16) __nv_bfloat16 Bs[BKg][136];  // stride 272B

    int bz = blockIdx.z;
    int bm = blockIdx.y * BM;
    int bn = blockIdx.x * BN;
    const __nv_bfloat16* Ab = A + sA * bz;
    const __nv_bfloat16* Bb = Bm + sB * bz;

    int tid = threadIdx.x, lane = tid & 31, warp = tid >> 5;
    int wm = (warp & 1) * 64;   // 2 warps along M
    int wn = (warp >> 1) * 32;  // 4 warps along N

    float acc[4][4][4];
#pragma unroll
    for (int i = 0; i < 4; i++)
#pragma unroll
        for (int j = 0; j < 4; j++)
#pragma unroll
            for (int c = 0; c < 4; c++) acc[i][j][c] = 0.f;

    for (int k0 = 0; k0 < Kdim; k0 += BKg) {
#pragma unroll
        for (int i = 0; i < 4; i++) {
            int slot = tid + i * 256;
            int r  = slot >> 3, c  = (slot & 7) << 2;
            *(uint2*)&As[r][c] = *(const uint2*)(Ab + (size_t)(bm + r) * ldA + k0 + c);
            int r2 = slot >> 5, c2 = (slot & 31) << 2;
            *(uint2*)&Bs[r2][c2] = *(const uint2*)(Bb + (size_t)(k0 + r2) * ldB + bn + c2);
        }
        __syncthreads();
#pragma unroll
        for (int kk = 0; kk < BKg; kk += 16) {
            uint32_t af[4][4], bf[4][2];
            int ar = wm + (lane & 15);
            int ac = kk + ((lane >> 4) << 3);
#pragma unroll
            for (int mi = 0; mi < 4; mi++) {
                uint32_t ad = smem_u32(&As[ar + mi * 16][ac]);
                asm volatile("ldmatrix.sync.aligned.m8n8.x4.shared.b16 {%0,%1,%2,%3}, [%4];"
                             : "=r"(af[mi][0]), "=r"(af[mi][1]), "=r"(af[mi][2]), "=r"(af[mi][3])
                             : "r"(ad));
            }
            int br = kk + (lane & 15);
#pragma unroll
            for (int ni = 0; ni < 4; ni++) {
                uint32_t bd = smem_u32(&Bs[br][wn + ni * 8]);
                asm volatile("ldmatrix.sync.aligned.m8n8.x2.trans.shared.b16 {%0,%1}, [%2];"
                             : "=r"(bf[ni][0]), "=r"(bf[ni][1]) : "r"(bd));
            }
#pragma unroll
            for (int mi = 0; mi < 4; mi++)
#pragma unroll
                for (int ni = 0; ni < 4; ni++) {
                    float* d = acc[mi][ni];
                    asm volatile(
                        "mma.sync.aligned.m16n8k16.row.col.f32.bf16.bf16.f32 "
                        "{%0,%1,%2,%3}, {%4,%5,%6,%7}, {%8,%9}, {%0,%1,%2,%3};"
                        : "+f"(d[0]), "+f"(d[1]), "+f"(d[2]), "+f"(d[3])
                        : "r"(af[mi][0]), "r"(af[mi][1]), "r"(af[mi][2]), "r"(af[mi][3]),
                          "r"(bf[ni][0]), "r"(bf[ni][1]));
                }
        }
        __syncthreads();
    }

    int g = lane >> 2, t2 = (lane & 3) << 1;
#pragma unroll
    for (int mi = 0; mi < 4; mi++) {
#pragma unroll
        for (int ni = 0; ni < 4; ni++) {
            int row0 = bm + wm + mi * 16 + g;
            int col  = bn + wn + ni * 8 + t2;
            float* d = acc[mi][ni];
            if (MODE == 0) {
                float* C = (float*)Cv + sC * bz;
                *(float2*)&C[(size_t)row0 * ldC + col]       = make_float2(d[0], d[1]);
                *(float2*)&C[(size_t)(row0 + 8) * ldC + col] = make_float2(d[2], d[3]);
            } else if (MODE == 1) {
                __nv_bfloat16* C = (__nv_bfloat16*)Cv + sC * bz;
                const float* ax = aux + sAux * bz;
                float2 a0 = *(const float2*)&ax[(size_t)row0 * ldC + col];
                float2 a1 = *(const float2*)&ax[(size_t)(row0 + 8) * ldC + col];
                *(__nv_bfloat162*)&C[(size_t)row0 * ldC + col] =
                    __floats2bfloat162_rn(a0.x + 0.1f * d[0], a0.y + 0.1f * d[1]);
                *(__nv_bfloat162*)&C[(size_t)(row0 + 8) * ldC + col] =
                    __floats2bfloat162_rn(a1.x + 0.1f * d[2], a1.y + 0.1f * d[3]);
            } else {
                float* C = (float*)Cv + sC * bz;
                const float* ax = aux + sAux * bz;
                float2 a0 = *(const float2*)&ax[(size_t)row0 * ldC + col];
                float2 a1 = *(const float2*)&ax[(size_t)(row0 + 8) * ldC + col];
                *(float2*)&C[(size_t)row0 * ldC + col] =
                    make_float2(d[0] + 2.f * a0.x, d[1] + 2.f * a0.y);
                *(float2*)&C[(size_t)(row0 + 8) * ldC + col] =
                    make_float2(d[2] + 2.f * a1.x, d[3] + 2.f * a1.y);
            }
        }
    }
}

// ---------------- LayerNorm over D=1024, in place on d_out ----------------
__global__ void k_ln(float* __restrict__ y, const float* __restrict__ gamma,
                     const float* __restrict__ beta) {
    int row = blockIdx.x;                          // b*S + s
    float4* p = (float4*)(y + (size_t)row * DD);
    int t = threadIdx.x;                           // 256
    float4 v = p[t];
    float s1 = v.x + v.y + v.z + v.w;
    float s2 = v.x * v.x + v.y * v.y + v.z * v.z + v.w * v.w;
#pragma unroll
    for (int o = 16; o > 0; o >>= 1) {
        s1 += __shfl_down_sync(0xffffffffu, s1, o);
        s2 += __shfl_down_sync(0xffffffffu, s2, o);
    }
    __shared__ float r1[8], r2[8];
    int w = t >> 5, l = t & 31;
    if (l == 0) { r1[w] = s1; r2[w] = s2; }
    __syncthreads();
    float mu = 0.f, m2 = 0.f;
#pragma unroll
    for (int i = 0; i < 8; i++) { mu += r1[i]; m2 += r2[i]; }
    mu *= (1.0f / (float)DD);
    float var = m2 * (1.0f / (float)DD) - mu * mu;
    float rs = rsqrtf(var + 1e-5f);
    float4 g = ((const float4*)gamma)[t];
    float4 bb = ((const float4*)beta)[t];
    v.x = (v.x - mu) * rs * g.x + bb.x;
    v.y = (v.y - mu) * rs * g.y + bb.y;
    v.z = (v.z - mu) * rs * g.z + bb.z;
    v.w = (v.w - mu) * rs * g.w + bb.w;
    p[t] = v;
}

// ---------------- launch ----------------
extern "C" void kernel_launch(void* const* d_in, const int* in_sizes, int n_in,
                              void* d_out, int out_size) {
    const float* x     = (const float*)d_in[0];
    const float* mag   = (const float*)d_in[1];
    const float* ph    = (const float*)d_in[2];
    const float* W     = (const float*)d_in[3];
    const float* gamma = (const float*)d_in[4];
    const float* beta  = (const float*)d_in[5];
    float* out = (float*)d_out;

    void *p_b1, *p_b2, *p_wt, *p_xbf, *p_X, *p_xwr, *p_dp, *p_dl;
    cudaGetSymbolAddress(&p_b1, g_basis1);
    cudaGetSymbolAddress(&p_b2, g_basis2);
    cudaGetSymbolAddress(&p_wt, g_wt);
    cudaGetSymbolAddress(&p_xbf, g_xbf);
    cudaGetSymbolAddress(&p_X, g_X);
    cudaGetSymbolAddress(&p_xwr, g_xwr);
    cudaGetSymbolAddress(&p_dp, g_dpart);
    cudaGetSymbolAddress(&p_dl, g_delta);

    // 1. bases + weight transpose + x->bf16
    k_basis<<<(K2 * SS) / 256, 256>>>();
    k_wt<<<(KK * KK) / 256, 256>>>(W);
    k_convert<<<(BB * SS * DD / 4) / 256, 256>>>(x);

    // 2. G1: X[b] (512x1024) = basis1 (512x2048) @ xbf[b] (2048x1024)
    gemm_mma<0><<<dim3(DD / BN, K2 / BM, BB), 256>>>(
        (const __nv_bfloat16*)p_b1, 0, SS,
        (const __nv_bfloat16*)p_xbf, (size_t)SS * DD, DD,
        p_X, (size_t)K2 * DD, DD,
        nullptr, 0, SS);

    // 3. elementwise complex weighting
    k_elem<<<(BB * KK * DD) / 256, 256>>>(mag, ph);

    // 4. interference: deltar[b] (256x1024) = dpart + 0.1 * (WT (256x256) @ xwr[b] (256x1024))
    gemm_mma<1><<<dim3(DD / BN, KK / BM, BB), 256>>>(
        (const __nv_bfloat16*)p_wt, 0, KK,
        (const __nv_bfloat16*)p_xwr, (size_t)KK * DD, DD,
        p_dl, (size_t)K2 * DD, DD,
        (const float*)p_dp, (size_t)KK * DD,
        KK);

    // 5. G2: y[b] (2048x1024) = basis2 (2048x512) @ delta[b] (512x1024) + 2*x[b]
    gemm_mma<2><<<dim3(DD / BN, SS / BM, BB), 256>>>(
        (const __nv_bfloat16*)p_b2, 0, K2,
        (const __nv_bfloat16*)p_dl, (size_t)K2 * DD, DD,
        d_out, (size_t)SS * DD, DD,
        x, (size_t)SS * DD,
        K2);

    // 6. LayerNorm in place
    k_ln<<<BB * SS, 256>>>(out, gamma, beta);
}

// round 2
// speedup vs baseline: 1.0841x; 1.0841x over previous
#include <cuda_runtime.h>
#include <cuda_bf16.h>
#include <cstdint>
#include <cstdio>

// Problem constants
#define BB   8
#define SS   2048
#define DD   1024
#define KK   256
#define NFFT 2048
#define K2   512   // 2*KK (stacked real/imag)

// ---------------- device scratch (no allocations allowed) ----------------
__device__ __align__(256) __nv_bfloat16 g_basis1[K2 * SS];        // A1[k][s]: rows 0..255 cos, 256..511 -sin
__device__ __align__(256) __nv_bfloat16 g_basis2[SS * K2];        // A2[s][j]: irfft basis with c_k/N folded in
__device__ __align__(256) __nv_bfloat16 g_wt[KK * KK];            // WT[j][k] = W[k][j]
__device__ __align__(256) __nv_bfloat16 g_xbf[BB * SS * DD];      // bf16(x)
__device__ __align__(256) float         g_X[BB * K2 * DD];        // Xr rows 0..255, Xi rows 256..511
__device__ __align__(256) __nv_bfloat16 g_xwr[BB * KK * DD];      // Re(x_weighted) bf16
__device__ __align__(256) float         g_dpart[BB * KK * DD];    // xwr - Xr (fp32, pre-interference)
__device__ __align__(256) __nv_bfloat16 g_delta[BB * K2 * DD];    // stacked [deltar; deltai] bf16

// ---------------- helpers ----------------
__device__ __forceinline__ int freq_of(int k) {
    // np.linspace(0, 512, 256).astype(int64); numpy pins the endpoint exactly.
    if (k == 255) return 512;
    return (int)((double)k * (512.0 / 255.0));
}

__device__ __forceinline__ uint32_t smem_u32(const void* p) {
    return (uint32_t)__cvta_generic_to_shared(p);
}

__device__ __forceinline__ void cp_async16(void* smem_dst, const void* gmem_src) {
    asm volatile("cp.async.cg.shared.global [%0], [%1], 16;\n"
                 :: "r"(smem_u32(smem_dst)), "l"(gmem_src));
}
__device__ __forceinline__ void cp_commit() {
    asm volatile("cp.async.commit_group;\n");
}
template <int N>
__device__ __forceinline__ void cp_wait() {
    asm volatile("cp.async.wait_group %0;\n" :: "n"(N));
}

// ---------------- basis construction (runs every launch; deterministic) ----------------
__global__ void k_basis() {
    int idx = blockIdx.x * blockDim.x + threadIdx.x;
    if (idx >= K2 * SS) return;
    int row = idx >> 11;       // 0..511
    int s   = idx & 2047;
    int k   = row & 255;
    int f   = freq_of(k);
    int m   = (f * s) & (NFFT - 1);
    float ang = (float)m * (6.28318530717958647692f / (float)NFFT);
    float sv, cv;
    sincosf(ang, &sv, &cv);
    // forward DFT basis: Xr = sum cos * x ; Xi = -sum sin * x
    float v1 = (row < KK) ? cv : -sv;
    g_basis1[idx] = __float2bfloat16(v1);
    // inverse (irfft of sparse delta): (c_k/N) * (cos*Re - sin*Im)
    float scale = ((k == 0) ? 1.0f : 2.0f) * (1.0f / (float)NFFT);
    float v2 = (row < KK) ? (scale * cv) : (-scale * sv);
    g_basis2[s * K2 + row] = __float2bfloat16(v2);
}

__global__ void k_wt(const float* __restrict__ W) {
    int idx = blockIdx.x * blockDim.x + threadIdx.x;   // 65536
    if (idx >= KK * KK) return;
    int j = idx >> 8, k = idx & 255;
    g_wt[idx] = __float2bfloat16(W[k * KK + j]);
}

__global__ void k_convert(const float* __restrict__ x) {
    int i = blockIdx.x * blockDim.x + threadIdx.x;     // over float4s
    if (i >= (BB * SS * DD) / 4) return;
    float4 v = ((const float4*)x)[i];
    __nv_bfloat162* o = (__nv_bfloat162*)g_xbf;
    o[2 * i]     = __floats2bfloat162_rn(v.x, v.y);
    o[2 * i + 1] = __floats2bfloat162_rn(v.z, v.w);
}

// elementwise: complex weight, imag delta, partial real delta
__global__ void k_elem(const float* __restrict__ mag, const float* __restrict__ ph) {
    int idx = blockIdx.x * blockDim.x + threadIdx.x;   // BB*KK*DD = 2M
    if (idx >= BB * KK * DD) return;
    int b = idx >> 18;
    int r = idx & 262143;
    int k = r >> 10;
    int d = r & 1023;
    size_t xb = (size_t)b * (K2 * DD);
    float Xr = g_X[xb + ((size_t)k << 10) + d];
    float Xi = g_X[xb + ((size_t)(k + KK) << 10) + d];
    float mg = mag[(k << 10) + d];
    float p  = ph[(k << 10) + d];
    float sp, cp;
    sincosf(p, &sp, &cp);
    float cr = mg * cp, ci = mg * sp;
    float xwr = Xr * cr - Xi * ci;
    float xwi = Xr * ci + Xi * cr;
    g_xwr[idx]   = __float2bfloat16(xwr);
    g_dpart[idx] = xwr - Xr;
    g_delta[xb + ((size_t)(k + KK) << 10) + d] = __float2bfloat16(xwi - Xi);
}

// ---------------- tiled bf16 mma GEMM, cp.async double-buffered ----------------
// C[m][n] = sum_k A[m][k] * B[k][n]
// MODE 0: fp32 store (G1)
// MODE 1: bf16 store: aux + 0.1*acc (interference -> deltar)
// MODE 2: fp32 store: acc + 2*aux   (irfft contrib + residual*2)
#define BM 128
#define BN 128
#define BKg 32

template <int MODE>
__global__ __launch_bounds__(256) void gemm_mma(
    const __nv_bfloat16* __restrict__ A, size_t sA, int ldA,
    const __nv_bfloat16* __restrict__ Bm, size_t sB, int ldB,
    void* __restrict__ Cv, size_t sC, int ldC,
    const float* __restrict__ aux, size_t sAux,
    int Kdim)
{
    // stage-padded smem; row strides are multiples of 16B and conflict-skewed
    __shared__ __align__(16) __nv_bfloat16 As[2][BM][40];    // 80B stride
    __shared__ __align__(16) __nv_bfloat16 Bs[2][BKg][136];  // 272B stride

    int bz = blockIdx.z;
    int bm = blockIdx.y * BM;
    int bn = blockIdx.x * BN;
    const __nv_bfloat16* Ab = A + sA * bz;
    const __nv_bfloat16* Bb = Bm + sB * bz;

    int tid = threadIdx.x, lane = tid & 31, warp = tid >> 5;
    int wm = (warp & 1) * 64;   // 2 warps along M
    int wn = (warp >> 1) * 32;  // 4 warps along N

    // per-thread cp.async coordinates (all shapes divide exactly)
    // A tile: 128 rows x 32 cols -> 512 x 16B chunks -> 2 per thread
    int a_r0 = tid >> 2;              // 0..63  (+64 second chunk)
    int a_c  = (tid & 3) << 3;        // {0,8,16,24}
    // B tile: 32 rows x 128 cols -> 512 x 16B chunks -> 2 per thread
    int b_r0 = tid >> 4;              // 0..15  (+16 second chunk)
    int b_c  = (tid & 15) << 3;       // 0..120 step 8

    float acc[4][4][4];
#pragma unroll
    for (int i = 0; i < 4; i++)
#pragma unroll
        for (int j = 0; j < 4; j++)
#pragma unroll
            for (int c = 0; c < 4; c++) acc[i][j][c] = 0.f;

    int nt = Kdim / BKg;

    // prefetch stage 0
    {
        int k0 = 0;
        cp_async16(&As[0][a_r0][a_c],      Ab + (size_t)(bm + a_r0) * ldA + k0 + a_c);
        cp_async16(&As[0][a_r0 + 64][a_c], Ab + (size_t)(bm + a_r0 + 64) * ldA + k0 + a_c);
        cp_async16(&Bs[0][b_r0][b_c],      Bb + (size_t)(k0 + b_r0) * ldB + bn + b_c);
        cp_async16(&Bs[0][b_r0 + 16][b_c], Bb + (size_t)(k0 + b_r0 + 16) * ldB + bn + b_c);
        cp_commit();
    }

    for (int kt = 0; kt < nt; kt++) {
        int buf = kt & 1;
        if (kt + 1 < nt) {
            int k0 = (kt + 1) * BKg;
            int nb = buf ^ 1;
            cp_async16(&As[nb][a_r0][a_c],      Ab + (size_t)(bm + a_r0) * ldA + k0 + a_c);
            cp_async16(&As[nb][a_r0 + 64][a_c], Ab + (size_t)(bm + a_r0 + 64) * ldA + k0 + a_c);
            cp_async16(&Bs[nb][b_r0][b_c],      Bb + (size_t)(k0 + b_r0) * ldB + bn + b_c);
            cp_async16(&Bs[nb][b_r0 + 16][b_c], Bb + (size_t)(k0 + b_r0 + 16) * ldB + bn + b_c);
            cp_commit();
            cp_wait<1>();   // stage kt complete, kt+1 in flight
        } else {
            cp_wait<0>();
        }
        __syncthreads();

#pragma unroll
        for (int kk = 0; kk < BKg; kk += 16) {
            uint32_t af[4][4], bf[4][2];
            int ar = wm + (lane & 15);
            int ac = kk + ((lane >> 4) << 3);
#pragma unroll
            for (int mi = 0; mi < 4; mi++) {
                uint32_t ad = smem_u32(&As[buf][ar + mi * 16][ac]);
                asm volatile("ldmatrix.sync.aligned.m8n8.x4.shared.b16 {%0,%1,%2,%3}, [%4];"
                             : "=r"(af[mi][0]), "=r"(af[mi][1]), "=r"(af[mi][2]), "=r"(af[mi][3])
                             : "r"(ad));
            }
            int br = kk + (lane & 15);
#pragma unroll
            for (int ni = 0; ni < 4; ni++) {
                uint32_t bd = smem_u32(&Bs[buf][br][wn + ni * 8]);
                asm volatile("ldmatrix.sync.aligned.m8n8.x2.trans.shared.b16 {%0,%1}, [%2];"
                             : "=r"(bf[ni][0]), "=r"(bf[ni][1]) : "r"(bd));
            }
#pragma unroll
            for (int mi = 0; mi < 4; mi++)
#pragma unroll
                for (int ni = 0; ni < 4; ni++) {
                    float* d = acc[mi][ni];
                    asm volatile(
                        "mma.sync.aligned.m16n8k16.row.col.f32.bf16.bf16.f32 "
                        "{%0,%1,%2,%3}, {%4,%5,%6,%7}, {%8,%9}, {%0,%1,%2,%3};"
                        : "+f"(d[0]), "+f"(d[1]), "+f"(d[2]), "+f"(d[3])
                        : "r"(af[mi][0]), "r"(af[mi][1]), "r"(af[mi][2]), "r"(af[mi][3]),
                          "r"(bf[ni][0]), "r"(bf[ni][1]));
                }
        }
        __syncthreads();
    }

    int g = lane >> 2, t2 = (lane & 3) << 1;
#pragma unroll
    for (int mi = 0; mi < 4; mi++) {
#pragma unroll
        for (int ni = 0; ni < 4; ni++) {
            int row0 = bm + wm + mi * 16 + g;
            int col  = bn + wn + ni * 8 + t2;
            float* d = acc[mi][ni];
            if (MODE == 0) {
                float* C = (float*)Cv + sC * bz;
                *(float2*)&C[(size_t)row0 * ldC + col]       = make_float2(d[0], d[1]);
                *(float2*)&C[(size_t)(row0 + 8) * ldC + col] = make_float2(d[2], d[3]);
            } else if (MODE == 1) {
                __nv_bfloat16* C = (__nv_bfloat16*)Cv + sC * bz;
                const float* ax = aux + sAux * bz;
                float2 a0 = *(const float2*)&ax[(size_t)row0 * ldC + col];
                float2 a1 = *(const float2*)&ax[(size_t)(row0 + 8) * ldC + col];
                *(__nv_bfloat162*)&C[(size_t)row0 * ldC + col] =
                    __floats2bfloat162_rn(a0.x + 0.1f * d[0], a0.y + 0.1f * d[1]);
                *(__nv_bfloat162*)&C[(size_t)(row0 + 8) * ldC + col] =
                    __floats2bfloat162_rn(a1.x + 0.1f * d[2], a1.y + 0.1f * d[3]);
            } else {
                float* C = (float*)Cv + sC * bz;
                const float* ax = aux + sAux * bz;
                float2 a0 = *(const float2*)&ax[(size_t)row0 * ldC + col];
                float2 a1 = *(const float2*)&ax[(size_t)(row0 + 8) * ldC + col];
                *(float2*)&C[(size_t)row0 * ldC + col] =
                    make_float2(d[0] + 2.f * a0.x, d[1] + 2.f * a0.y);
                *(float2*)&C[(size_t)(row0 + 8) * ldC + col] =
                    make_float2(d[2] + 2.f * a1.x, d[3] + 2.f * a1.y);
            }
        }
    }
}

// ---------------- LayerNorm over D=1024, in place on d_out ----------------
__global__ void k_ln(float* __restrict__ y, const float* __restrict__ gamma,
                     const float* __restrict__ beta) {
    int row = blockIdx.x;                          // b*S + s
    float4* p = (float4*)(y + (size_t)row * DD);
    int t = threadIdx.x;                           // 256
    float4 v = p[t];
    float s1 = v.x + v.y + v.z + v.w;
    float s2 = v.x * v.x + v.y * v.y + v.z * v.z + v.w * v.w;
#pragma unroll
    for (int o = 16; o > 0; o >>= 1) {
        s1 += __shfl_down_sync(0xffffffffu, s1, o);
        s2 += __shfl_down_sync(0xffffffffu, s2, o);
    }
    __shared__ float r1[8], r2[8];
    int w = t >> 5, l = t & 31;
    if (l == 0) { r1[w] = s1; r2[w] = s2; }
    __syncthreads();
    float mu = 0.f, m2 = 0.f;
#pragma unroll
    for (int i = 0; i < 8; i++) { mu += r1[i]; m2 += r2[i]; }
    mu *= (1.0f / (float)DD);
    float var = m2 * (1.0f / (float)DD) - mu * mu;
    float rs = rsqrtf(var + 1e-5f);
    float4 g = ((const float4*)gamma)[t];
    float4 bb = ((const float4*)beta)[t];
    v.x = (v.x - mu) * rs * g.x + bb.x;
    v.y = (v.y - mu) * rs * g.y + bb.y;
    v.z = (v.z - mu) * rs * g.z + bb.z;
    v.w = (v.w - mu) * rs * g.w + bb.w;
    p[t] = v;
}

// ---------------- launch ----------------
extern "C" void kernel_launch(void* const* d_in, const int* in_sizes, int n_in,
                              void* d_out, int out_size) {
    const float* x     = (const float*)d_in[0];
    const float* mag   = (const float*)d_in[1];
    const float* ph    = (const float*)d_in[2];
    const float* W     = (const float*)d_in[3];
    const float* gamma = (const float*)d_in[4];
    const float* beta  = (const float*)d_in[5];
    float* out = (float*)d_out;

    void *p_b1, *p_b2, *p_wt, *p_xbf, *p_X, *p_xwr, *p_dp, *p_dl;
    cudaGetSymbolAddress(&p_b1, g_basis1);
    cudaGetSymbolAddress(&p_b2, g_basis2);
    cudaGetSymbolAddress(&p_wt, g_wt);
    cudaGetSymbolAddress(&p_xbf, g_xbf);
    cudaGetSymbolAddress(&p_X, g_X);
    cudaGetSymbolAddress(&p_xwr, g_xwr);
    cudaGetSymbolAddress(&p_dp, g_dpart);
    cudaGetSymbolAddress(&p_dl, g_delta);

    // 1. bases + weight transpose + x->bf16
    k_basis<<<(K2 * SS) / 256, 256>>>();
    k_wt<<<(KK * KK) / 256, 256>>>(W);
    k_convert<<<(BB * SS * DD / 4) / 256, 256>>>(x);

    // 2. G1: X[b] (512x1024) = basis1 (512x2048) @ xbf[b] (2048x1024)
    gemm_mma<0><<<dim3(DD / BN, K2 / BM, BB), 256>>>(
        (const __nv_bfloat16*)p_b1, 0, SS,
        (const __nv_bfloat16*)p_xbf, (size_t)SS * DD, DD,
        p_X, (size_t)K2 * DD, DD,
        nullptr, 0, SS);

    // 3. elementwise complex weighting
    k_elem<<<(BB * KK * DD) / 256, 256>>>(mag, ph);

    // 4. interference: deltar[b] (256x1024) = dpart + 0.1 * (WT (256x256) @ xwr[b] (256x1024))
    gemm_mma<1><<<dim3(DD / BN, KK / BM, BB), 256>>>(
        (const __nv_bfloat16*)p_wt, 0, KK,
        (const __nv_bfloat16*)p_xwr, (size_t)KK * DD, DD,
        p_dl, (size_t)K2 * DD, DD,
        (const float*)p_dp, (size_t)KK * DD,
        KK);

    // 5. G2: y[b] (2048x1024) = basis2 (2048x512) @ delta[b] (512x1024) + 2*x[b]
    gemm_mma<2><<<dim3(DD / BN, SS / BM, BB), 256>>>(
        (const __nv_bfloat16*)p_b2, 0, K2,
        (const __nv_bfloat16*)p_dl, (size_t)K2 * DD, DD,
        d_out, (size_t)SS * DD, DD,
        x, (size_t)SS * DD,
        K2);

    // 6. LayerNorm in place
    k_ln<<<BB * SS, 256>>>(out, gamma, beta);
}

// round 4
// speedup vs baseline: 1.1250x; 1.0378x over previous
#include <cuda_runtime.h>
#include <cuda_bf16.h>
#include <cstdint>
#include <cstdio>

// Problem constants
#define BB   8
#define SS   2048
#define DD   1024
#define KK   256
#define NFFT 2048
#define K2   512   // 2*KK (stacked real/imag)

// ---------------- device scratch (no allocations allowed) ----------------
__device__ __align__(256) __nv_bfloat16 g_basis1[K2 * SS];        // A1[k][s]
__device__ __align__(256) __nv_bfloat16 g_basis2[SS * K2];        // A2[s][j]
__device__ __align__(256) __nv_bfloat16 g_wt[KK * KK];            // WT[j][k] = W[k][j]
__device__ __align__(256) __nv_bfloat16 g_xbf[BB * SS * DD];      // bf16(x)
__device__ __align__(256) float         g_X[BB * K2 * DD];        // Xr rows 0..255, Xi rows 256..511
__device__ __align__(256) __nv_bfloat16 g_xwr[BB * KK * DD];      // Re(x_weighted) bf16
__device__ __align__(256) float         g_dpart[BB * KK * DD];    // xwr - Xr
__device__ __align__(256) __nv_bfloat16 g_delta[BB * K2 * DD];    // stacked [deltar; deltai] bf16

// ---------------- helpers ----------------
__device__ __forceinline__ int freq_of(int k) {
    if (k == 255) return 512;
    return (int)((double)k * (512.0 / 255.0));
}
__device__ __forceinline__ uint32_t smem_u32(const void* p) {
    return (uint32_t)__cvta_generic_to_shared(p);
}
__device__ __forceinline__ void cp_async16(void* smem_dst, const void* gmem_src) {
    asm volatile("cp.async.cg.shared.global [%0], [%1], 16;\n"
                 :: "r"(smem_u32(smem_dst)), "l"(gmem_src));
}
__device__ __forceinline__ void cp_commit() {
    asm volatile("cp.async.commit_group;\n");
}
template <int N>
__device__ __forceinline__ void cp_wait() {
    asm volatile("cp.async.wait_group %0;\n" :: "n"(N));
}

// ---------------- basis construction ----------------
__global__ void k_basis() {
    int idx = blockIdx.x * blockDim.x + threadIdx.x;
    if (idx >= K2 * SS) return;
    int row = idx >> 11;
    int s   = idx & 2047;
    int k   = row & 255;
    int f   = freq_of(k);
    int m   = (f * s) & (NFFT - 1);
    float ang = (float)m * (6.28318530717958647692f / (float)NFFT);
    float sv, cv;
    sincosf(ang, &sv, &cv);
    float v1 = (row < KK) ? cv : -sv;
    g_basis1[idx] = __float2bfloat16(v1);
    float scale = ((k == 0) ? 1.0f : 2.0f) * (1.0f / (float)NFFT);
    float v2 = (row < KK) ? (scale * cv) : (-scale * sv);
    g_basis2[s * K2 + row] = __float2bfloat16(v2);
}

__global__ void k_wt(const float* __restrict__ W) {
    int idx = blockIdx.x * blockDim.x + threadIdx.x;
    if (idx >= KK * KK) return;
    int j = idx >> 8, k = idx & 255;
    g_wt[idx] = __float2bfloat16(W[k * KK + j]);
}

__global__ void k_convert(const float* __restrict__ x) {
    int i = blockIdx.x * blockDim.x + threadIdx.x;
    if (i >= (BB * SS * DD) / 4) return;
    float4 v = ((const float4*)x)[i];
    __nv_bfloat162* o = (__nv_bfloat162*)g_xbf;
    o[2 * i]     = __floats2bfloat162_rn(v.x, v.y);
    o[2 * i + 1] = __floats2bfloat162_rn(v.z, v.w);
}

// elementwise: complex weight, imag delta, partial real delta
__global__ void k_elem(const float* __restrict__ mag, const float* __restrict__ ph) {
    int idx = blockIdx.x * blockDim.x + threadIdx.x;
    if (idx >= BB * KK * DD) return;
    int b = idx >> 18;
    int r = idx & 262143;
    int k = r >> 10;
    int d = r & 1023;
    size_t xb = (size_t)b * (K2 * DD);
    float Xr = g_X[xb + ((size_t)k << 10) + d];
    float Xi = g_X[xb + ((size_t)(k + KK) << 10) + d];
    float mg = mag[(k << 10) + d];
    float p  = ph[(k << 10) + d];
    float sp, cp;
    sincosf(p, &sp, &cp);
    float cr = mg * cp, ci = mg * sp;
    float xwr = Xr * cr - Xi * ci;
    float xwi = Xr * ci + Xi * cr;
    g_xwr[idx]   = __float2bfloat16(xwr);
    g_dpart[idx] = xwr - Xr;
    g_delta[xb + ((size_t)(k + KK) << 10) + d] = __float2bfloat16(xwi - Xi);
}

// ---------------- tiled bf16 mma GEMM, 4-stage cp.async pipeline ----------------
// C[m][n] = sum_k A[m][k] * B[k][n]
// MODE 0: fp32 store (G1)
// MODE 1: bf16 store: aux + 0.1*acc (interference -> deltar)
// MODE 2: fp32 store: acc + 2*aux   (irfft contrib + residual*2)
#define BM 128
#define BN 128
#define BKg 32
#define NSTG 4
#define A_BYTES (BM * 40 * 2)      // 10240
#define B_BYTES (BKg * 136 * 2)    // 8704
#define GEMM_SMEM (NSTG * (A_BYTES + B_BYTES))   // 75776

template <int MODE>
__global__ __launch_bounds__(256, 2) void gemm_mma(
    const __nv_bfloat16* __restrict__ A, size_t sA, int ldA,
    const __nv_bfloat16* __restrict__ Bm, size_t sB, int ldB,
    void* __restrict__ Cv, size_t sC, int ldC,
    const float* __restrict__ aux, size_t sAux,
    int Kdim)
{
    extern __shared__ __align__(16) char dsm[];

    int bz = blockIdx.z;
    int bm = blockIdx.y * BM;
    int bn = blockIdx.x * BN;
    const __nv_bfloat16* Ab = A + sA * bz;
    const __nv_bfloat16* Bb = Bm + sB * bz;

    int tid = threadIdx.x, lane = tid & 31, warp = tid >> 5;
    int wm = (warp & 1) * 64;   // 2 warps along M
    int wn = (warp >> 1) * 32;  // 4 warps along N

    // per-thread cp.async coordinates
    int a_r0 = tid >> 2;              // 0..63  (+64 second chunk)
    int a_c  = (tid & 3) << 3;        // {0,8,16,24}
    int b_r0 = tid >> 4;              // 0..15  (+16 second chunk)
    int b_c  = (tid & 15) << 3;       // 0..120 step 8

    float acc[4][4][4];
#pragma unroll
    for (int i = 0; i < 4; i++)
#pragma unroll
        for (int j = 0; j < 4; j++)
#pragma unroll
            for (int c = 0; c < 4; c++) acc[i][j][c] = 0.f;

    int nt = Kdim / BKg;

    // stage base pointers
    auto a_base = [&](int st) -> char* { return dsm + st * A_BYTES; };
    auto b_base = [&](int st) -> char* { return dsm + NSTG * A_BYTES + st * B_BYTES; };

    auto load_stage = [&](int s) {
        char* ap = a_base(s & (NSTG - 1));
        char* bp = b_base(s & (NSTG - 1));
        int k0 = s * BKg;
        cp_async16(ap + (a_r0 * 40 + a_c) * 2,        Ab + (size_t)(bm + a_r0) * ldA + k0 + a_c);
        cp_async16(ap + ((a_r0 + 64) * 40 + a_c) * 2, Ab + (size_t)(bm + a_r0 + 64) * ldA + k0 + a_c);
        cp_async16(bp + (b_r0 * 136 + b_c) * 2,        Bb + (size_t)(k0 + b_r0) * ldB + bn + b_c);
        cp_async16(bp + ((b_r0 + 16) * 136 + b_c) * 2, Bb + (size_t)(k0 + b_r0 + 16) * ldB + bn + b_c);
        cp_commit();
    };

    // prologue: stages 0..NSTG-2 in flight
#pragma unroll
    for (int i = 0; i < NSTG - 1; i++) load_stage(i);

    for (int kt = 0; kt < nt; kt++) {
        cp_wait<NSTG - 2>();        // stage kt complete (2 newer stages may remain in flight)
        __syncthreads();            // all warps done computing stage kt-1; stage kt visible
        // issue lookahead load into the buffer freed by stage kt-1
        if (kt + NSTG - 1 < nt) load_stage(kt + NSTG - 1);
        else                    cp_commit();   // keep group accounting uniform

        char* ap = a_base(kt & (NSTG - 1));
        char* bp = b_base(kt & (NSTG - 1));

#pragma unroll
        for (int kk = 0; kk < BKg; kk += 16) {
            uint32_t af[4][4], bf[4][2];
            int ar = wm + (lane & 15);
            int ac = kk + ((lane >> 4) << 3);
#pragma unroll
            for (int mi = 0; mi < 4; mi++) {
                uint32_t ad = smem_u32(ap + ((ar + mi * 16) * 40 + ac) * 2);
                asm volatile("ldmatrix.sync.aligned.m8n8.x4.shared.b16 {%0,%1,%2,%3}, [%4];"
                             : "=r"(af[mi][0]), "=r"(af[mi][1]), "=r"(af[mi][2]), "=r"(af[mi][3])
                             : "r"(ad));
            }
            int br = kk + (lane & 15);
#pragma unroll
            for (int ni = 0; ni < 4; ni++) {
                uint32_t bd = smem_u32(bp + (br * 136 + wn + ni * 8) * 2);
                asm volatile("ldmatrix.sync.aligned.m8n8.x2.trans.shared.b16 {%0,%1}, [%2];"
                             : "=r"(bf[ni][0]), "=r"(bf[ni][1]) : "r"(bd));
            }
#pragma unroll
            for (int mi = 0; mi < 4; mi++)
#pragma unroll
                for (int ni = 0; ni < 4; ni++) {
                    float* d = acc[mi][ni];
                    asm volatile(
                        "mma.sync.aligned.m16n8k16.row.col.f32.bf16.bf16.f32 "
                        "{%0,%1,%2,%3}, {%4,%5,%6,%7}, {%8,%9}, {%0,%1,%2,%3};"
                        : "+f"(d[0]), "+f"(d[1]), "+f"(d[2]), "+f"(d[3])
                        : "r"(af[mi][0]), "r"(af[mi][1]), "r"(af[mi][2]), "r"(af[mi][3]),
                          "r"(bf[ni][0]), "r"(bf[ni][1]));
                }
        }
    }

    int g = lane >> 2, t2 = (lane & 3) << 1;
#pragma unroll
    for (int mi = 0; mi < 4; mi++) {
#pragma unroll
        for (int ni = 0; ni < 4; ni++) {
            int row0 = bm + wm + mi * 16 + g;
            int col  = bn + wn + ni * 8 + t2;
            float* d = acc[mi][ni];
            if (MODE == 0) {
                float* C = (float*)Cv + sC * bz;
                *(float2*)&C[(size_t)row0 * ldC + col]       = make_float2(d[0], d[1]);
                *(float2*)&C[(size_t)(row0 + 8) * ldC + col] = make_float2(d[2], d[3]);
            } else if (MODE == 1) {
                __nv_bfloat16* C = (__nv_bfloat16*)Cv + sC * bz;
                const float* ax = aux + sAux * bz;
                float2 a0 = *(const float2*)&ax[(size_t)row0 * ldC + col];
                float2 a1 = *(const float2*)&ax[(size_t)(row0 + 8) * ldC + col];
                *(__nv_bfloat162*)&C[(size_t)row0 * ldC + col] =
                    __floats2bfloat162_rn(a0.x + 0.1f * d[0], a0.y + 0.1f * d[1]);
                *(__nv_bfloat162*)&C[(size_t)(row0 + 8) * ldC + col] =
                    __floats2bfloat162_rn(a1.x + 0.1f * d[2], a1.y + 0.1f * d[3]);
            } else {
                float* C = (float*)Cv + sC * bz;
                const float* ax = aux + sAux * bz;
                float2 a0 = *(const float2*)&ax[(size_t)row0 * ldC + col];
                float2 a1 = *(const float2*)&ax[(size_t)(row0 + 8) * ldC + col];
                *(float2*)&C[(size_t)row0 * ldC + col] =
                    make_float2(d[0] + 2.f * a0.x, d[1] + 2.f * a0.y);
                *(float2*)&C[(size_t)(row0 + 8) * ldC + col] =
                    make_float2(d[2] + 2.f * a1.x, d[3] + 2.f * a1.y);
            }
        }
    }
}

// ---------------- LayerNorm over D=1024, in place on d_out ----------------
__global__ void k_ln(float* __restrict__ y, const float* __restrict__ gamma,
                     const float* __restrict__ beta) {
    int row = blockIdx.x;
    float4* p = (float4*)(y + (size_t)row * DD);
    int t = threadIdx.x;
    float4 v = p[t];
    float s1 = v.x + v.y + v.z + v.w;
    float s2 = v.x * v.x + v.y * v.y + v.z * v.z + v.w * v.w;
#pragma unroll
    for (int o = 16; o > 0; o >>= 1) {
        s1 += __shfl_down_sync(0xffffffffu, s1, o);
        s2 += __shfl_down_sync(0xffffffffu, s2, o);
    }
    __shared__ float r1[8], r2[8];
    int w = t >> 5, l = t & 31;
    if (l == 0) { r1[w] = s1; r2[w] = s2; }
    __syncthreads();
    float mu = 0.f, m2 = 0.f;
#pragma unroll
    for (int i = 0; i < 8; i++) { mu += r1[i]; m2 += r2[i]; }
    mu *= (1.0f / (float)DD);
    float var = m2 * (1.0f / (float)DD) - mu * mu;
    float rs = rsqrtf(var + 1e-5f);
    float4 g = ((const float4*)gamma)[t];
    float4 bb = ((const float4*)beta)[t];
    v.x = (v.x - mu) * rs * g.x + bb.x;
    v.y = (v.y - mu) * rs * g.y + bb.y;
    v.z = (v.z - mu) * rs * g.z + bb.z;
    v.w = (v.w - mu) * rs * g.w + bb.w;
    p[t] = v;
}

// ---------------- launch ----------------
extern "C" void kernel_launch(void* const* d_in, const int* in_sizes, int n_in,
                              void* d_out, int out_size) {
    const float* x     = (const float*)d_in[0];
    const float* mag   = (const float*)d_in[1];
    const float* ph    = (const float*)d_in[2];
    const float* W     = (const float*)d_in[3];
    const float* gamma = (const float*)d_in[4];
    const float* beta  = (const float*)d_in[5];
    float* out = (float*)d_out;

    void *p_b1, *p_b2, *p_wt, *p_xbf, *p_X, *p_xwr, *p_dp, *p_dl;
    cudaGetSymbolAddress(&p_b1, g_basis1);
    cudaGetSymbolAddress(&p_b2, g_basis2);
    cudaGetSymbolAddress(&p_wt, g_wt);
    cudaGetSymbolAddress(&p_xbf, g_xbf);
    cudaGetSymbolAddress(&p_X, g_X);
    cudaGetSymbolAddress(&p_xwr, g_xwr);
    cudaGetSymbolAddress(&p_dp, g_dpart);
    cudaGetSymbolAddress(&p_dl, g_delta);

    cudaFuncSetAttribute(gemm_mma<0>, cudaFuncAttributeMaxDynamicSharedMemorySize, GEMM_SMEM);
    cudaFuncSetAttribute(gemm_mma<1>, cudaFuncAttributeMaxDynamicSharedMemorySize, GEMM_SMEM);
    cudaFuncSetAttribute(gemm_mma<2>, cudaFuncAttributeMaxDynamicSharedMemorySize, GEMM_SMEM);

    // 1. bases + weight transpose + x->bf16
    k_basis<<<(K2 * SS) / 256, 256>>>();
    k_wt<<<(KK * KK) / 256, 256>>>(W);
    k_convert<<<(BB * SS * DD / 4) / 256, 256>>>(x);

    // 2. G1: X[b] (512x1024) = basis1 (512x2048) @ xbf[b] (2048x1024)
    gemm_mma<0><<<dim3(DD / BN, K2 / BM, BB), 256, GEMM_SMEM>>>(
        (const __nv_bfloat16*)p_b1, 0, SS,
        (const __nv_bfloat16*)p_xbf, (size_t)SS * DD, DD,
        p_X, (size_t)K2 * DD, DD,
        nullptr, 0, SS);

    // 3. elementwise complex weighting
    k_elem<<<(BB * KK * DD) / 256, 256>>>(mag, ph);

    // 4. interference: deltar[b] (256x1024) = dpart + 0.1 * (WT (256x256) @ xwr[b] (256x1024))
    gemm_mma<1><<<dim3(DD / BN, KK / BM, BB), 256, GEMM_SMEM>>>(
        (const __nv_bfloat16*)p_wt, 0, KK,
        (const __nv_bfloat16*)p_xwr, (size_t)KK * DD, DD,
        p_dl, (size_t)K2 * DD, DD,
        (const float*)p_dp, (size_t)KK * DD,
        KK);

    // 5. G2: y[b] (2048x1024) = basis2 (2048x512) @ delta[b] (512x1024) + 2*x[b]
    gemm_mma<2><<<dim3(DD / BN, SS / BM, BB), 256, GEMM_SMEM>>>(
        (const __nv_bfloat16*)p_b2, 0, K2,
        (const __nv_bfloat16*)p_dl, (size_t)K2 * DD, DD,
        d_out, (size_t)SS * DD, DD,
        x, (size_t)SS * DD,
        K2);

    // 6. LayerNorm in place
    k_ln<<<BB * SS, 256>>>(out, gamma, beta);
}